// round 3
// baseline (speedup 1.0000x reference)
#include <cuda_runtime.h>
#include <math.h>

#define B_   8
#define T_   512
#define FIN_ 256
#define D_   128
#define C_   16          // chunks per batch
#define L_   32          // chunk length (T_/C_)

// ---------------- scratch (device globals; no runtime allocation) ----------------
__device__ __align__(16) float g_XN[B_*T_*FIN_];   // normalized x
__device__ __align__(16) float g_K[B_*T_*D_];
__device__ __align__(16) float g_Q[B_*T_*D_];
__device__ __align__(16) float g_V[B_*T_*D_];
__device__ __align__(16) float g_R[B_*T_*D_];      // xn @ Ws + bs
__device__ __align__(16) float g_num[B_*T_*D_];    // numerator
__device__ __align__(16) float g_den[B_*T_];       // denominator (pre +1e-5)
__device__ __align__(16) float g_Soff[B_*C_*D_*D_];// chunk sums -> exclusive prefix
__device__ __align__(16) float g_Zsum[B_*C_*D_];   // chunk K sums -> exclusive prefix

// ---------------- k0: LayerNorm -> g_XN ----------------
__global__ void k0_ln(const float* __restrict__ x,
                      const float* __restrict__ gamma, const float* __restrict__ beta) {
    const int tid  = threadIdx.x;
    const int w    = tid >> 5, lane = tid & 31;
    const int row0 = blockIdx.x * 32;

    float gv[8], bv[8];
#pragma unroll
    for (int k = 0; k < 8; k++) { gv[k] = gamma[lane + 32*k]; bv[k] = beta[lane + 32*k]; }

#pragma unroll
    for (int rr = 0; rr < 4; rr++) {
        const size_t r = (size_t)row0 + w*4 + rr;
        float s = 0.f, ss = 0.f, xv[8];
#pragma unroll
        for (int k = 0; k < 8; k++) {
            float v = x[r*FIN_ + lane + 32*k];
            xv[k] = v; s += v; ss += v*v;
        }
#pragma unroll
        for (int off = 16; off; off >>= 1) {
            s  += __shfl_xor_sync(0xffffffffu, s,  off);
            ss += __shfl_xor_sync(0xffffffffu, ss, off);
        }
        const float mu   = s * (1.0f/FIN_);
        const float rstd = rsqrtf(ss*(1.0f/FIN_) - mu*mu + 1e-5f);
#pragma unroll
        for (int k = 0; k < 8; k++)
            g_XN[r*FIN_ + lane + 32*k] = (xv[k]-mu)*rstd*gv[k] + bv[k];
    }
}

// ---------------- k1: projections. PAIR=0 -> {K,V}, PAIR=1 -> {Q,R} ----------------
// grid (128, 2) x 128 threads, 32 rows/block, micro-tile 4x8
template<int PAIR>
__global__ void k1_proj(const float* __restrict__ Wk, const float* __restrict__ Wq,
                        const float* __restrict__ Wv, const float* __restrict__ Ws,
                        const float* __restrict__ bs) {
    extern __shared__ float sm[];
    float* xb = sm;               // 32*256
    float* wb = sm + 32*FIN_;     // 32*128
    const int tid = threadIdx.x;       // 128
    const int tr  = tid >> 4;          // 0..7
    const int tc  = tid & 15;          // 0..15
    const int row0 = blockIdx.x * 32;
    const int m    = PAIR + 2*blockIdx.y;   // 0:K 1:Q 2:V 3:R

    const float* Wp = (m==0) ? Wk : (m==1) ? Wq : (m==2) ? Wv : Ws;
    float*       Op = (m==0) ? g_K : (m==1) ? g_Q : (m==2) ? g_V : g_R;

    {
        const float4* xg = (const float4*)(g_XN + (size_t)row0 * FIN_);
        for (int q = tid; q < 32*FIN_/4; q += 128) ((float4*)xb)[q] = xg[q];
    }

    float acc[4][8];
#pragma unroll
    for (int u = 0; u < 4; u++)
#pragma unroll
        for (int v = 0; v < 8; v++) acc[u][v] = 0.f;

    for (int kc = 0; kc < FIN_; kc += 32) {
        __syncthreads();
        for (int q = tid; q < 32*D_/4; q += 128)
            ((float4*)wb)[q] = ((const float4*)(Wp + (size_t)kc*D_))[q];
        __syncthreads();
#pragma unroll
        for (int k = 0; k < 32; k++) {
            const float4 wA = ((const float4*)(wb + k*D_))[tc*2];
            const float4 wB = ((const float4*)(wb + k*D_))[tc*2+1];
#pragma unroll
            for (int u = 0; u < 4; u++) {
                const float a = xb[(tr*4+u)*FIN_ + kc + k];
                acc[u][0] += a*wA.x; acc[u][1] += a*wA.y;
                acc[u][2] += a*wA.z; acc[u][3] += a*wA.w;
                acc[u][4] += a*wB.x; acc[u][5] += a*wB.y;
                acc[u][6] += a*wB.z; acc[u][7] += a*wB.w;
            }
        }
    }

    float badd[8] = {0,0,0,0,0,0,0,0};
    if (m == 3) {
        float4 t0 = ((const float4*)bs)[tc*2];
        float4 t1 = ((const float4*)bs)[tc*2+1];
        badd[0]=t0.x; badd[1]=t0.y; badd[2]=t0.z; badd[3]=t0.w;
        badd[4]=t1.x; badd[5]=t1.y; badd[6]=t1.z; badd[7]=t1.w;
    }
#pragma unroll
    for (int u = 0; u < 4; u++) {
        float o[8];
#pragma unroll
        for (int v = 0; v < 8; v++) {
            float val = acc[u][v];
            if (m <= 1) val = (val > 0.f) ? (val + 1.f) : expf(val);   // elu + 1
            o[v] = val + badd[v];
        }
        float* dst = Op + ((size_t)(row0 + tr*4 + u))*D_ + tc*8;
        *(float4*)(dst)   = make_float4(o[0], o[1], o[2], o[3]);
        *(float4*)(dst+4) = make_float4(o[4], o[5], o[6], o[7]);
    }
}

// ---------------- k2: per-chunk outer-product sums + per-chunk K sums ----------------
__global__ void k2_chunksum() {
    const int c = blockIdx.x, b = blockIdx.y;
    const int tid = threadIdx.x;   // 256
    __shared__ __align__(16) float Ks[L_][D_];
    __shared__ __align__(16) float Vs[L_][D_];
    {
        const float4* kg = (const float4*)(g_K + ((size_t)b*T_ + c*L_)*D_);
        const float4* vg = (const float4*)(g_V + ((size_t)b*T_ + c*L_)*D_);
        for (int q = tid; q < L_*D_/4; q += 256) { ((float4*)Ks)[q] = kg[q]; ((float4*)Vs)[q] = vg[q]; }
    }
    __syncthreads();

    if (tid < D_) {
        float zs = 0.f;
#pragma unroll
        for (int t = 0; t < L_; t++) zs += Ks[t][tid];
        g_Zsum[((size_t)(b*C_ + c))*D_ + tid] = zs;
    }

    const int tr = tid >> 4, tc = tid & 15;  // 16x16, micro 8x8
    const int i0 = tr*8, j0 = tc*8;
    float acc[8][8];
#pragma unroll
    for (int u = 0; u < 8; u++)
#pragma unroll
        for (int v = 0; v < 8; v++) acc[u][v] = 0.f;

    for (int t = 0; t < L_; t++) {
        float k8[8], v8[8];
        *(float4*)(k8)   = *(const float4*)&Ks[t][i0];
        *(float4*)(k8+4) = *(const float4*)&Ks[t][i0+4];
        *(float4*)(v8)   = *(const float4*)&Vs[t][j0];
        *(float4*)(v8+4) = *(const float4*)&Vs[t][j0+4];
#pragma unroll
        for (int u = 0; u < 8; u++)
#pragma unroll
            for (int v = 0; v < 8; v++) acc[u][v] += k8[u]*v8[v];
    }
    float* op = g_Soff + (((size_t)(b*C_ + c))*D_ + i0)*D_ + j0;
#pragma unroll
    for (int u = 0; u < 8; u++) {
        *(float4*)(op + (size_t)u*D_)     = make_float4(acc[u][0],acc[u][1],acc[u][2],acc[u][3]);
        *(float4*)(op + (size_t)u*D_ + 4) = make_float4(acc[u][4],acc[u][5],acc[u][6],acc[u][7]);
    }
}

// ---------------- k3: exclusive scan over c, register-blocked (MLP=16) ----------------
__global__ void k3_scan() {
    const int gid = blockIdx.x * blockDim.x + threadIdx.x;
    if (gid < B_*D_*D_) {
        const int b  = gid >> 14;
        const int ij = gid & (D_*D_ - 1);
        float* p = g_Soff + (size_t)b*C_*D_*D_ + ij;
        float v[C_];
#pragma unroll
        for (int c = 0; c < C_; c++) v[c] = p[(size_t)c*D_*D_];
        float run = 0.f;
#pragma unroll
        for (int c = 0; c < C_; c++) { const float t = v[c]; v[c] = run; run += t; }
#pragma unroll
        for (int c = 0; c < C_; c++) p[(size_t)c*D_*D_] = v[c];
    } else if (gid < B_*D_*D_ + B_*D_) {
        const int zid = gid - B_*D_*D_;
        const int b = zid >> 7, i = zid & (D_-1);
        float* p = g_Zsum + (size_t)b*C_*D_ + i;
        float v[C_];
#pragma unroll
        for (int c = 0; c < C_; c++) v[c] = p[(size_t)c*D_];
        float run = 0.f;
#pragma unroll
        for (int c = 0; c < C_; c++) { const float t = v[c]; v[c] = run; run += t; }
#pragma unroll
        for (int c = 0; c < C_; c++) p[(size_t)c*D_] = v[c];
    }
}

// ---------------- k4: pure streaming scan — S state in regs, write S + Z, NO inner syncs ----------------
__global__ void __launch_bounds__(1024, 1)
k4_main(const float* __restrict__ S0, const float* __restrict__ Z0,
        float* __restrict__ outS, float* __restrict__ outZ) {
    const int c = blockIdx.x, b = blockIdx.y;
    const int tid = threadIdx.x;         // 1024
    const int ri = tid >> 5;             // 0..31 (warp id)
    const int jg = tid & 31;
    const int i0 = ri << 2, j0 = jg << 2;

    __shared__ __align__(16) float Ks[L_*D_];
    __shared__ __align__(16) float Vs[L_*D_];

    const size_t base = ((size_t)b*T_ + c*L_)*D_;
    for (int q = tid; q < L_*D_/4; q += 1024) {
        ((float4*)Ks)[q] = ((const float4*)(g_K + base))[q];
        ((float4*)Vs)[q] = ((const float4*)(g_V + base))[q];
    }

    float s[4][4];
    {
        const float* soff = g_Soff + ((size_t)(b*C_ + c)*D_ + i0)*D_ + j0;
        const float* s0g  = S0 + ((size_t)b*D_ + i0)*D_ + j0;
#pragma unroll
        for (int u = 0; u < 4; u++) {
            const float4 a = *(const float4*)(soff + (size_t)u*D_);
            const float4 z = *(const float4*)(s0g  + (size_t)u*D_);
            s[u][0] = a.x + z.x; s[u][1] = a.y + z.y;
            s[u][2] = a.z + z.z; s[u][3] = a.w + z.w;
        }
    }

    float zrun = 0.f;
    if (tid < D_) zrun = Z0[b*D_ + tid] + g_Zsum[(size_t)(b*C_ + c)*D_ + tid];
    __syncthreads();

    float* op = outS + ((size_t)(b*T_ + c*L_))*D_*D_ + (size_t)i0*D_ + j0;
    float* zp = outZ + base;

    for (int tt = 0; tt < L_; tt++) {
        const float4 kv = *(const float4*)&Ks[tt*D_ + i0];   // broadcast within warp
        const float4 vv = *(const float4*)&Vs[tt*D_ + j0];   // conflict-free
        const float kk[4] = {kv.x, kv.y, kv.z, kv.w};
#pragma unroll
        for (int u = 0; u < 4; u++) {
            s[u][0] += kk[u]*vv.x;
            s[u][1] += kk[u]*vv.y;
            s[u][2] += kk[u]*vv.z;
            s[u][3] += kk[u]*vv.w;
            __stcs((float4*)(op + (size_t)u*D_),
                   make_float4(s[u][0], s[u][1], s[u][2], s[u][3]));
        }
        if (tid < D_) { zrun += Ks[tt*D_ + tid]; zp[tid] = zrun; }
        op += (size_t)D_*D_;
        zp += D_;
    }
}

// ---------------- kN: numerator + denominator per chunk (runs concurrent with k4) ----------------
// num[t] = Q[t]@(S0+Soff) + masked(QK^T)@V ; den[t] = Q[t]@(Z0+Zoff) + rowsum(masked QK^T)
#define KN_SMEM ((3*L_*D_ + 32*D_ + L_*L_ + D_) * 4)
__global__ void __launch_bounds__(256)
kN_numden(const float* __restrict__ S0, const float* __restrict__ Z0) {
    const int c = blockIdx.x, b = blockIdx.y;
    const int tid = threadIdx.x;   // 256
    extern __shared__ float dsm[];
    float* Qs = dsm;               // L*D
    float* Ks = Qs + L_*D_;        // L*D
    float* Vs = Ks + L_*D_;        // L*D
    float* Sb = Vs + L_*D_;        // 32*D
    float* A  = Sb + 32*D_;        // L*L
    float* zv = A + L_*L_;         // D

    const size_t base = ((size_t)b*T_ + c*L_)*D_;
    for (int q = tid; q < L_*D_/4; q += 256) {
        ((float4*)Qs)[q] = ((const float4*)(g_Q + base))[q];
        ((float4*)Ks)[q] = ((const float4*)(g_K + base))[q];
        ((float4*)Vs)[q] = ((const float4*)(g_V + base))[q];
    }
    if (tid < D_) zv[tid] = Z0[b*D_ + tid] + g_Zsum[(size_t)(b*C_ + c)*D_ + tid];
    __syncthreads();

    const int ti = tid >> 3;       // 0..31 (row)
    const int g  = tid & 7;        // 0..7

    // A[ti][g*4..g*4+3] = Q[ti]·K[tj], masked tj<=ti; plus rowsum and z-dot
    float a4[4] = {0.f, 0.f, 0.f, 0.f};
    for (int k = 0; k < D_; k += 4) {
        const float4 qv = *(const float4*)&Qs[ti*D_ + k];
#pragma unroll
        for (int j = 0; j < 4; j++) {
            const float4 kv = *(const float4*)&Ks[(g*4+j)*D_ + k];
            a4[j] += qv.x*kv.x + qv.y*kv.y + qv.z*kv.z + qv.w*kv.w;
        }
    }
    float rsum = 0.f;
#pragma unroll
    for (int j = 0; j < 4; j++) {
        const int tj = g*4 + j;
        const float m = (tj <= ti) ? a4[j] : 0.f;
        A[ti*L_ + tj] = m;
        rsum += m;
    }
    float zp = 0.f;
#pragma unroll
    for (int k = 0; k < 16; k += 4) {
        const float4 qv = *(const float4*)&Qs[ti*D_ + g*16 + k];
        const float4 zz = *(const float4*)&zv[g*16 + k];
        zp += qv.x*zz.x + qv.y*zz.y + qv.z*zz.z + qv.w*zz.w;
    }
    float tot = rsum + zp;
#pragma unroll
    for (int off = 4; off; off >>= 1) tot += __shfl_down_sync(0xffffffffu, tot, off);
    if (g == 0) g_den[(size_t)b*T_ + c*L_ + ti] = tot;
    __syncthreads();

    // num[ti][c0..c0+15]
    const int row = ti;
    const int c0  = g * 16;
    float acc[16];
#pragma unroll
    for (int v = 0; v < 16; v++) acc[v] = 0.f;

    // intra: masked A @ V
    for (int tj = 0; tj <= row; tj++) {
        const float a = A[row*L_ + tj];
#pragma unroll
        for (int v = 0; v < 16; v += 4) {
            const float4 vv = *(const float4*)&Vs[tj*D_ + c0 + v];
            acc[v]   += a*vv.x; acc[v+1] += a*vv.y;
            acc[v+2] += a*vv.z; acc[v+3] += a*vv.w;
        }
    }
    // inter: Q @ (S0 + Soff)
    const float* s0p = S0 + (size_t)b*D_*D_;
    const float* sop = g_Soff + (size_t)(b*C_ + c)*D_*D_;
    for (int kb = 0; kb < D_; kb += 32) {
        __syncthreads();
        for (int q = tid; q < 32*D_/4; q += 256) {
            const float4 x0 = ((const float4*)(s0p + (size_t)kb*D_))[q];
            const float4 x1 = ((const float4*)(sop + (size_t)kb*D_))[q];
            ((float4*)Sb)[q] = make_float4(x0.x+x1.x, x0.y+x1.y, x0.z+x1.z, x0.w+x1.w);
        }
        __syncthreads();
        for (int k = 0; k < 32; k++) {
            const float qq = Qs[row*D_ + kb + k];
#pragma unroll
            for (int v = 0; v < 16; v += 4) {
                const float4 sv = *(const float4*)&Sb[k*D_ + c0 + v];
                acc[v]   += qq*sv.x; acc[v+1] += qq*sv.y;
                acc[v+2] += qq*sv.z; acc[v+3] += qq*sv.w;
            }
        }
    }
    float* np = g_num + base + (size_t)row*D_ + c0;
#pragma unroll
    for (int v = 0; v < 16; v += 4)
        *(float4*)(np + v) = make_float4(acc[v], acc[v+1], acc[v+2], acc[v+3]);
}

// ---------------- k5: out = relu(relu((num/den)@W1+b1)@W2+b2) + R ----------------
__global__ void k5_ffn(const float* __restrict__ W1, const float* __restrict__ b1_,
                       const float* __restrict__ W2, const float* __restrict__ b2_,
                       float* __restrict__ outO) {
    __shared__ __align__(16) float aBuf[32*D_];
    __shared__ __align__(16) float wBuf[32*D_];
    const int tid  = threadIdx.x;  // 256
    const int w    = tid >> 5, lane = tid & 31;
    const int row0 = blockIdx.x * 32;

#pragma unroll
    for (int rr = 0; rr < 4; rr++) {
        const int r = w*4 + rr;
        const size_t row = (size_t)row0 + r;
        const float rden = 1.0f / (g_den[row] + 1e-5f);
#pragma unroll
        for (int k = 0; k < 4; k++) {
            const int f = lane + 32*k;
            aBuf[r*D_ + f] = g_num[row*D_ + f] * rden;
        }
    }
    const int rowg = w, colg = lane;
    float acc[4][4];

#pragma unroll
    for (int u = 0; u < 4; u++)
#pragma unroll
        for (int v = 0; v < 4; v++) acc[u][v] = 0.f;
    for (int kc = 0; kc < D_; kc += 32) {
        __syncthreads();
        for (int q = tid; q < 32*D_/4; q += 256)
            ((float4*)wBuf)[q] = ((const float4*)(W1 + (size_t)kc*D_))[q];
        __syncthreads();
#pragma unroll
        for (int k = 0; k < 32; k++) {
            const float4 wv = ((const float4*)(wBuf + k*D_))[colg];
#pragma unroll
            for (int u = 0; u < 4; u++) {
                const float a = aBuf[(rowg*4+u)*D_ + kc + k];
                acc[u][0] += a*wv.x; acc[u][1] += a*wv.y;
                acc[u][2] += a*wv.z; acc[u][3] += a*wv.w;
            }
        }
    }
    __syncthreads();
    {
        const float4 b1v = ((const float4*)b1_)[colg];
#pragma unroll
        for (int u = 0; u < 4; u++) {
            float4 h;
            h.x = fmaxf(acc[u][0] + b1v.x, 0.f);
            h.y = fmaxf(acc[u][1] + b1v.y, 0.f);
            h.z = fmaxf(acc[u][2] + b1v.z, 0.f);
            h.w = fmaxf(acc[u][3] + b1v.w, 0.f);
            *(float4*)&aBuf[(rowg*4+u)*D_ + colg*4] = h;
        }
    }
#pragma unroll
    for (int u = 0; u < 4; u++)
#pragma unroll
        for (int v = 0; v < 4; v++) acc[u][v] = 0.f;
    for (int kc = 0; kc < D_; kc += 32) {
        __syncthreads();
        for (int q = tid; q < 32*D_/4; q += 256)
            ((float4*)wBuf)[q] = ((const float4*)(W2 + (size_t)kc*D_))[q];
        __syncthreads();
#pragma unroll
        for (int k = 0; k < 32; k++) {
            const float4 wv = ((const float4*)(wBuf + k*D_))[colg];
#pragma unroll
            for (int u = 0; u < 4; u++) {
                const float a = aBuf[(rowg*4+u)*D_ + kc + k];
                acc[u][0] += a*wv.x; acc[u][1] += a*wv.y;
                acc[u][2] += a*wv.z; acc[u][3] += a*wv.w;
            }
        }
    }
    {
        const float4 b2v = ((const float4*)b2_)[colg];
#pragma unroll
        for (int u = 0; u < 4; u++) {
            const size_t row = (size_t)row0 + rowg*4 + u;
            const float4 rv = *(const float4*)(g_R + row*D_ + colg*4);
            float4 o;
            o.x = fmaxf(acc[u][0] + b2v.x, 0.f) + rv.x;
            o.y = fmaxf(acc[u][1] + b2v.y, 0.f) + rv.y;
            o.z = fmaxf(acc[u][2] + b2v.z, 0.f) + rv.z;
            o.w = fmaxf(acc[u][3] + b2v.w, 0.f) + rv.w;
            *(float4*)(outO + row*D_ + colg*4) = o;
        }
    }
}

// ---------------- launch ----------------
static cudaStream_t s2 = nullptr;
static cudaEvent_t eA = nullptr, eB = nullptr, eD = nullptr;

extern "C" void kernel_launch(void* const* d_in, const int* in_sizes, int n_in,
                              void* d_out, int out_size) {
    const float* x     = (const float*)d_in[0];
    const float* S0    = (const float*)d_in[1];
    const float* Z0    = (const float*)d_in[2];
    const float* gamma = (const float*)d_in[3];
    const float* beta  = (const float*)d_in[4];
    const float* Wk    = (const float*)d_in[5];
    const float* Wq    = (const float*)d_in[6];
    const float* Wv    = (const float*)d_in[7];
    const float* W1    = (const float*)d_in[8];
    const float* b1    = (const float*)d_in[9];
    const float* W2    = (const float*)d_in[10];
    const float* b2    = (const float*)d_in[11];
    const float* Ws    = (const float*)d_in[12];
    const float* bs    = (const float*)d_in[13];

    float* outO = (float*)d_out;                       // [B,T,D]
    float* outS = outO + (size_t)B_*T_*D_;             // [B,T,D*D]
    float* outZ = outS + (size_t)B_*T_*D_*D_;          // [B,T,D]

    if (!s2) {   // one-time resource setup (runs during the correctness call, before capture)
        cudaStreamCreateWithFlags(&s2, cudaStreamNonBlocking);
        cudaEventCreateWithFlags(&eA, cudaEventDisableTiming);
        cudaEventCreateWithFlags(&eB, cudaEventDisableTiming);
        cudaEventCreateWithFlags(&eD, cudaEventDisableTiming);
        cudaFuncSetAttribute(kN_numden, cudaFuncAttributeMaxDynamicSharedMemorySize, KN_SMEM);
    }

    const int smem_k1 = (32*FIN_ + 32*D_) * sizeof(float);   // 49152 bytes

    // stream 0 (capture origin): LN -> K,V proj -> chunk sums -> scan -> big S/Z write
    k0_ln<<<(B_*T_)/32, 256>>>(x, gamma, beta);
    cudaEventRecord(eA, 0);
    k1_proj<0><<<dim3((B_*T_)/32, 2), 128, smem_k1>>>(Wk, Wq, Wv, Ws, bs);  // K, V
    k2_chunksum<<<dim3(C_, B_), 256>>>();
    k3_scan<<<(B_*D_*D_ + B_*D_ + 255)/256, 256>>>();
    cudaEventRecord(eB, 0);

    // stream 2: Q,R proj (after LN), then num/den + FFN (after scan) — overlaps k4
    cudaStreamWaitEvent(s2, eA, 0);
    k1_proj<1><<<dim3((B_*T_)/32, 2), 128, smem_k1, s2>>>(Wk, Wq, Wv, Ws, bs);  // Q, R
    cudaStreamWaitEvent(s2, eB, 0);
    kN_numden<<<dim3(C_, B_), 256, KN_SMEM, s2>>>(S0, Z0);
    k5_ffn<<<(B_*T_)/32, 256, 0, s2>>>(W1, b1, W2, b2, outO);
    cudaEventRecord(eD, s2);

    // stream 0: the DRAM-bound S/Z writer, concurrent with kN/k5
    k4_main<<<dim3(C_, B_), 1024>>>(S0, Z0, outS, outZ);
    cudaStreamWaitEvent(0, eD, 0);
}

// round 4
// speedup vs baseline: 1.1074x; 1.1074x over previous
#include <cuda_runtime.h>
#include <math.h>

#define B_   8
#define T_   512
#define FIN_ 256
#define D_   128
#define C_   16          // chunks per batch
#define L_   32          // chunk length (T_/C_)

typedef unsigned long long u64;

// ---------------- f32x2 packed helpers ----------------
__device__ __forceinline__ void fma2(u64& acc, u64 a, u64 b) {
    asm("fma.rn.f32x2 %0, %1, %2, %3;" : "=l"(acc) : "l"(a), "l"(b), "l"(acc));
}
__device__ __forceinline__ u64 bc2(float a) {
    u64 r; asm("mov.b64 %0, {%1, %1};" : "=l"(r) : "f"(a)); return r;
}
__device__ __forceinline__ float2 unp2(u64 v) {
    float2 r; asm("mov.b64 {%0, %1}, %2;" : "=f"(r.x), "=f"(r.y) : "l"(v)); return r;
}

// ---------------- scratch ----------------
__device__ __align__(16) float g_K[B_*T_*D_];
__device__ __align__(16) float g_Q[B_*T_*D_];
__device__ __align__(16) float g_V[B_*T_*D_];
__device__ __align__(16) float g_R[B_*T_*D_];      // xn @ Ws + bs
__device__ __align__(16) float g_Soff[B_*C_*D_*D_];// chunk sums -> exclusive prefix
__device__ __align__(16) float g_Zsum[B_*C_*D_];   // chunk K sums -> exclusive prefix

// ---------------- k1: fused LayerNorm + projection (m = blockIdx.y) ----------------
// grid (128, 4) x 128 threads; 32 rows/block; f32x2 inner product
__global__ void k1_ln_proj(const float* __restrict__ x,
                           const float* __restrict__ gamma, const float* __restrict__ beta,
                           const float* __restrict__ Wk, const float* __restrict__ Wq,
                           const float* __restrict__ Wv, const float* __restrict__ Ws,
                           const float* __restrict__ bs) {
    extern __shared__ float sm[];
    float* xb = sm;               // 32*256
    float* wb = sm + 32*FIN_;     // 32*128
    const int tid = threadIdx.x;       // 128
    const int w   = tid >> 5, lane = tid & 31;
    const int tr  = tid >> 4;          // 0..7
    const int tc  = tid & 15;          // 0..15
    const int row0 = blockIdx.x * 32;
    const int m    = blockIdx.y;       // 0:K 1:Q 2:V 3:R

    const float* Wp = (m==0) ? Wk : (m==1) ? Wq : (m==2) ? Wv : Ws;
    float*       Op = (m==0) ? g_K : (m==1) ? g_Q : (m==2) ? g_V : g_R;

    // load x tile
    {
        const float4* xg = (const float4*)(x + (size_t)row0 * FIN_);
        for (int q = tid; q < 32*FIN_/4; q += 128) ((float4*)xb)[q] = xg[q];
    }
    float gv[8], bv[8];
#pragma unroll
    for (int k = 0; k < 8; k++) { gv[k] = gamma[lane + 32*k]; bv[k] = beta[lane + 32*k]; }
    __syncthreads();

    // LayerNorm in-place: each warp owns 8 rows
#pragma unroll
    for (int rr = 0; rr < 8; rr++) {
        const int r = w*8 + rr;
        float s = 0.f, ss = 0.f, xv[8];
#pragma unroll
        for (int k = 0; k < 8; k++) { float v = xb[r*FIN_ + lane + 32*k]; xv[k] = v; s += v; ss += v*v; }
#pragma unroll
        for (int off = 16; off; off >>= 1) {
            s  += __shfl_xor_sync(0xffffffffu, s,  off);
            ss += __shfl_xor_sync(0xffffffffu, ss, off);
        }
        const float mu   = s * (1.0f/FIN_);
        const float rstd = rsqrtf(ss*(1.0f/FIN_) - mu*mu + 1e-5f);
#pragma unroll
        for (int k = 0; k < 8; k++)
            xb[r*FIN_ + lane + 32*k] = (xv[k]-mu)*rstd*gv[k] + bv[k];
    }
    __syncthreads();

    u64 acc2[4][4];
#pragma unroll
    for (int u = 0; u < 4; u++)
#pragma unroll
        for (int p = 0; p < 4; p++) acc2[u][p] = 0ull;

    for (int kc = 0; kc < FIN_; kc += 32) {
        __syncthreads();
        for (int q = tid; q < 32*D_/4; q += 128)
            ((float4*)wb)[q] = ((const float4*)(Wp + (size_t)kc*D_))[q];
        __syncthreads();
#pragma unroll
        for (int k = 0; k < 32; k++) {
            const ulonglong2 wA = ((const ulonglong2*)(wb + k*D_))[tc*2];
            const ulonglong2 wB = ((const ulonglong2*)(wb + k*D_))[tc*2+1];
#pragma unroll
            for (int u = 0; u < 4; u++) {
                const u64 aa = bc2(xb[(tr*4+u)*FIN_ + kc + k]);
                fma2(acc2[u][0], aa, wA.x);
                fma2(acc2[u][1], aa, wA.y);
                fma2(acc2[u][2], aa, wB.x);
                fma2(acc2[u][3], aa, wB.y);
            }
        }
    }

    float badd[8] = {0,0,0,0,0,0,0,0};
    if (m == 3) {
        float4 t0 = ((const float4*)bs)[tc*2];
        float4 t1 = ((const float4*)bs)[tc*2+1];
        badd[0]=t0.x; badd[1]=t0.y; badd[2]=t0.z; badd[3]=t0.w;
        badd[4]=t1.x; badd[5]=t1.y; badd[6]=t1.z; badd[7]=t1.w;
    }
#pragma unroll
    for (int u = 0; u < 4; u++) {
        float o[8];
#pragma unroll
        for (int p = 0; p < 4; p++) {
            const float2 t = unp2(acc2[u][p]);
            o[2*p] = t.x; o[2*p+1] = t.y;
        }
#pragma unroll
        for (int v = 0; v < 8; v++) {
            float val = o[v];
            if (m <= 1) val = (val > 0.f) ? (val + 1.f) : expf(val);   // elu + 1
            o[v] = val + badd[v];
        }
        float* dst = Op + ((size_t)(row0 + tr*4 + u))*D_ + tc*8;
        *(float4*)(dst)   = make_float4(o[0], o[1], o[2], o[3]);
        *(float4*)(dst+4) = make_float4(o[4], o[5], o[6], o[7]);
    }
}

// ---------------- k2: per-chunk outer-product sums + per-chunk K sums ----------------
__global__ void k2_chunksum() {
    const int c = blockIdx.x, b = blockIdx.y;
    const int tid = threadIdx.x;   // 256
    __shared__ __align__(16) float Ks[L_][D_];
    __shared__ __align__(16) float Vs[L_][D_];
    {
        const float4* kg = (const float4*)(g_K + ((size_t)b*T_ + c*L_)*D_);
        const float4* vg = (const float4*)(g_V + ((size_t)b*T_ + c*L_)*D_);
        for (int q = tid; q < L_*D_/4; q += 256) { ((float4*)Ks)[q] = kg[q]; ((float4*)Vs)[q] = vg[q]; }
    }
    __syncthreads();

    if (tid < D_) {
        float zs = 0.f;
#pragma unroll
        for (int t = 0; t < L_; t++) zs += Ks[t][tid];
        g_Zsum[((size_t)(b*C_ + c))*D_ + tid] = zs;
    }

    const int tr = tid >> 4, tc = tid & 15;  // 16x16, micro 8x8
    const int i0 = tr*8, j0 = tc*8;
    float acc[8][8];
#pragma unroll
    for (int u = 0; u < 8; u++)
#pragma unroll
        for (int v = 0; v < 8; v++) acc[u][v] = 0.f;

    for (int t = 0; t < L_; t++) {
        float k8[8], v8[8];
        *(float4*)(k8)   = *(const float4*)&Ks[t][i0];
        *(float4*)(k8+4) = *(const float4*)&Ks[t][i0+4];
        *(float4*)(v8)   = *(const float4*)&Vs[t][j0];
        *(float4*)(v8+4) = *(const float4*)&Vs[t][j0+4];
#pragma unroll
        for (int u = 0; u < 8; u++)
#pragma unroll
            for (int v = 0; v < 8; v++) acc[u][v] += k8[u]*v8[v];
    }
    float* op = g_Soff + (((size_t)(b*C_ + c))*D_ + i0)*D_ + j0;
#pragma unroll
    for (int u = 0; u < 8; u++) {
        *(float4*)(op + (size_t)u*D_)     = make_float4(acc[u][0],acc[u][1],acc[u][2],acc[u][3]);
        *(float4*)(op + (size_t)u*D_ + 4) = make_float4(acc[u][4],acc[u][5],acc[u][6],acc[u][7]);
    }
}

// ---------------- k3: exclusive scan over c, float4-wide ----------------
__global__ void k3_scan() {
    const int gid = blockIdx.x * blockDim.x + threadIdx.x;
    if (gid < B_*D_*D_/4) {                 // 32768
        const int b = gid >> 12;            // 4096 float4 per (b, c) slice
        const int q = gid & 4095;
        float4* p = ((float4*)g_Soff) + (size_t)b*C_*4096 + q;
        float4 v[C_];
#pragma unroll
        for (int c = 0; c < C_; c++) v[c] = p[(size_t)c*4096];
        float rx=0.f, ry=0.f, rz=0.f, rw=0.f;
#pragma unroll
        for (int c = 0; c < C_; c++) {
            const float4 t = v[c];
            v[c] = make_float4(rx, ry, rz, rw);
            rx += t.x; ry += t.y; rz += t.z; rw += t.w;
        }
#pragma unroll
        for (int c = 0; c < C_; c++) p[(size_t)c*4096] = v[c];
    } else if (gid < B_*D_*D_/4 + B_*D_/4) {
        const int zid = gid - B_*D_*D_/4;   // 0..255
        const int b = zid >> 5, q = zid & 31;
        float4* p = ((float4*)g_Zsum) + (size_t)b*C_*32 + q;
        float4 v[C_];
#pragma unroll
        for (int c = 0; c < C_; c++) v[c] = p[(size_t)c*32];
        float rx=0.f, ry=0.f, rz=0.f, rw=0.f;
#pragma unroll
        for (int c = 0; c < C_; c++) {
            const float4 t = v[c];
            v[c] = make_float4(rx, ry, rz, rw);
            rx += t.x; ry += t.y; rz += t.z; rw += t.w;
        }
#pragma unroll
        for (int c = 0; c < C_; c++) p[(size_t)c*32] = v[c];
    }
}

// ---------------- k4: MEGA kernel — streaming S/Z writes + num/den + FFN + out ----------------
// grid (C_, B_) x 1024 threads. smem: Ks,Vs,Qs (3x16KB) + A (4KB) + zv + sden
#define SMEM_K4 ((3*L_*D_ + L_*L_ + D_ + 32) * (int)sizeof(float))
__global__ void __launch_bounds__(1024, 1)
k4_mega(const float* __restrict__ S0, const float* __restrict__ Z0,
        const float* __restrict__ W1, const float* __restrict__ b1_,
        const float* __restrict__ W2, const float* __restrict__ b2_,
        float* __restrict__ outO, float* __restrict__ outS, float* __restrict__ outZ) {
    const int c = blockIdx.x, b = blockIdx.y;
    const int tid = threadIdx.x;         // 1024
    const int ri = tid >> 5;             // 0..31 (warp id == row)
    const int lane = tid & 31;
    const int i0 = ri << 2, j0 = lane << 2;

    extern __shared__ float dsm[];
    float* Ks   = dsm;                   // L_*D_ = 4096
    float* Vs   = Ks + L_*D_;
    float* Qs   = Vs + L_*D_;
    float* A    = Qs + L_*D_;            // 32x32
    float* zv   = A + L_*L_;             // 128
    float* sden = zv + D_;               // 32

    const size_t base = ((size_t)b*T_ + c*L_)*D_;

    // ---- load tiles: exactly one float4 per thread per array ----
    {
        const int q = tid;               // 1024 float4 = 4096 floats
        ((float4*)Ks)[q] = ((const float4*)(g_K + base))[q];
        ((float4*)Vs)[q] = ((const float4*)(g_V + base))[q];
        ((float4*)Qs)[q] = ((const float4*)(g_Q + base))[q];
    }

    // ---- init state ----
    float s[4][4];
    {
        const float* soff = g_Soff + ((size_t)(b*C_ + c)*D_ + i0)*D_ + j0;
        const float* s0g  = S0 + ((size_t)b*D_ + i0)*D_ + j0;
#pragma unroll
        for (int u = 0; u < 4; u++) {
            const float4 a = *(const float4*)(soff + (size_t)u*D_);
            const float4 z = *(const float4*)(s0g  + (size_t)u*D_);
            s[u][0] = a.x + z.x; s[u][1] = a.y + z.y;
            s[u][2] = a.z + z.z; s[u][3] = a.w + z.w;
        }
    }
    float zrun = 0.f;
    if (tid < D_) {
        zrun = Z0[b*D_ + tid] + g_Zsum[(size_t)(b*C_ + c)*D_ + tid];
        zv[tid] = zrun;                  // inter-chunk Z offset for den
    }
    __syncthreads();

    // ---- phase 1: streaming scan, no syncs ----
    {
        float* op = outS + ((size_t)(b*T_ + c*L_))*D_*D_ + (size_t)i0*D_ + j0;
        float* zp = outZ + base;
        for (int tt = 0; tt < L_; tt++) {
            const float4 kv = *(const float4*)&Ks[tt*D_ + i0];   // warp broadcast
            const float4 vv = *(const float4*)&Vs[tt*D_ + j0];   // conflict-free
            const float kk[4] = {kv.x, kv.y, kv.z, kv.w};
#pragma unroll
            for (int u = 0; u < 4; u++) {
                s[u][0] += kk[u]*vv.x;
                s[u][1] += kk[u]*vv.y;
                s[u][2] += kk[u]*vv.z;
                s[u][3] += kk[u]*vv.w;
                __stcs((float4*)(op + (size_t)u*D_),
                       make_float4(s[u][0], s[u][1], s[u][2], s[u][3]));
            }
            if (tid < D_) { zrun += Ks[tt*D_ + tid]; zp[tid] = zrun; }
            op += (size_t)D_*D_;
            zp += D_;
        }
    }

    // ---- phase 2a: masked A = QK^T, den (tid < 256: ti = row, g = col group) ----
    if (tid < 256) {
        const int ti = tid >> 3;
        const int g  = tid & 7;
        float a4[4] = {0.f, 0.f, 0.f, 0.f};
        for (int k = 0; k < D_; k += 4) {
            const float4 qv = *(const float4*)&Qs[ti*D_ + k];
#pragma unroll
            for (int j = 0; j < 4; j++) {
                const float4 kv = *(const float4*)&Ks[(g*4+j)*D_ + k];
                a4[j] += qv.x*kv.x + qv.y*kv.y + qv.z*kv.z + qv.w*kv.w;
            }
        }
        float rsum = 0.f;
#pragma unroll
        for (int j = 0; j < 4; j++) {
            const int tj = g*4 + j;
            const float mval = (tj <= ti) ? a4[j] : 0.f;
            A[ti*L_ + tj] = mval;
            rsum += mval;
        }
        float zp = 0.f;
#pragma unroll
        for (int k = 0; k < 16; k += 4) {
            const float4 qv = *(const float4*)&Qs[ti*D_ + g*16 + k];
            const float4 zz = *(const float4*)&zv[g*16 + k];
            zp += qv.x*zz.x + qv.y*zz.y + qv.z*zz.z + qv.w*zz.w;
        }
        float tot = rsum + zp;
#pragma unroll
        for (int off = 4; off; off >>= 1) tot += __shfl_down_sync(0xffffffffu, tot, off);
        if (g == 0) sden[ti] = tot;
    }
    __syncthreads();

    // ---- phase 2b: numerator. thread = (row=ri, cols j0..j0+3) ----
    float nacc[4] = {0.f, 0.f, 0.f, 0.f};
    // intra-chunk: masked A @ V
    for (int tj = 0; tj <= ri; tj++) {
        const float a = A[ri*L_ + tj];
        const float4 vv = ((const float4*)Vs)[tj*32 + lane];
        nacc[0] += a*vv.x; nacc[1] += a*vv.y;
        nacc[2] += a*vv.z; nacc[3] += a*vv.w;
    }
    // inter-chunk: Q @ (S0 + Soff), staged 32 rows at a time into Ks region
    {
        const float4* s0p = (const float4*)(S0 + (size_t)b*D_*D_);
        const float4* sop = (const float4*)(g_Soff + (size_t)(b*C_ + c)*D_*D_);
        for (int kb = 0; kb < D_; kb += 32) {
            __syncthreads();
            {
                const int q = tid;          // 1024 float4 = 32 rows x 32 float4
                const float4 x0 = __ldg(s0p + (size_t)kb*32 + q);
                const float4 x1 = __ldg(sop + (size_t)kb*32 + q);
                ((float4*)Ks)[q] = make_float4(x0.x+x1.x, x0.y+x1.y, x0.z+x1.z, x0.w+x1.w);
            }
            __syncthreads();
#pragma unroll 8
            for (int k = 0; k < 32; k++) {
                const float qq = Qs[ri*D_ + kb + k];
                const float4 sv = ((const float4*)Ks)[k*32 + lane];
                nacc[0] += qq*sv.x; nacc[1] += qq*sv.y;
                nacc[2] += qq*sv.z; nacc[3] += qq*sv.w;
            }
        }
    }
    // a = num / den  -> write into Qs region (each warp owns its own row)
    {
        const float rden = 1.0f / (sden[ri] + 1e-5f);
        ((float4*)Qs)[ri*32 + lane] = make_float4(nacc[0]*rden, nacc[1]*rden,
                                                  nacc[2]*rden, nacc[3]*rden);
    }
    __syncthreads();   // Qs(aBuf) visible; Ks free for hBuf

    // ---- phase 3: FFN. GEMM1: h = relu(a @ W1 + b1) ----
    {
        float4 acc = __ldg(((const float4*)b1_) + lane);
        for (int k = 0; k < D_; k++) {
            const float a = Qs[ri*D_ + k];
            const float4 wv = __ldg(((const float4*)(W1 + (size_t)k*D_)) + lane);
            acc.x += a*wv.x; acc.y += a*wv.y; acc.z += a*wv.z; acc.w += a*wv.w;
        }
        ((float4*)Ks)[ri*32 + lane] = make_float4(fmaxf(acc.x,0.f), fmaxf(acc.y,0.f),
                                                  fmaxf(acc.z,0.f), fmaxf(acc.w,0.f));
    }
    __syncwarp();      // hBuf row written cross-lane, read cross-lane within same warp only

    // ---- GEMM2: out = relu(h @ W2 + b2) + R ----
    {
        float4 acc = __ldg(((const float4*)b2_) + lane);
        for (int k = 0; k < D_; k++) {
            const float h = Ks[ri*D_ + k];
            const float4 wv = __ldg(((const float4*)(W2 + (size_t)k*D_)) + lane);
            acc.x += h*wv.x; acc.y += h*wv.y; acc.z += h*wv.z; acc.w += h*wv.w;
        }
        const size_t row = (size_t)b*T_ + c*L_ + ri;
        const float4 rv = *(const float4*)(g_R + row*D_ + j0);
        float4 o;
        o.x = fmaxf(acc.x, 0.f) + rv.x;
        o.y = fmaxf(acc.y, 0.f) + rv.y;
        o.z = fmaxf(acc.z, 0.f) + rv.z;
        o.w = fmaxf(acc.w, 0.f) + rv.w;
        *(float4*)(outO + row*D_ + j0) = o;
    }
}

// ---------------- launch ----------------
extern "C" void kernel_launch(void* const* d_in, const int* in_sizes, int n_in,
                              void* d_out, int out_size) {
    const float* x     = (const float*)d_in[0];
    const float* S0    = (const float*)d_in[1];
    const float* Z0    = (const float*)d_in[2];
    const float* gamma = (const float*)d_in[3];
    const float* beta  = (const float*)d_in[4];
    const float* Wk    = (const float*)d_in[5];
    const float* Wq    = (const float*)d_in[6];
    const float* Wv    = (const float*)d_in[7];
    const float* W1    = (const float*)d_in[8];
    const float* b1    = (const float*)d_in[9];
    const float* W2    = (const float*)d_in[10];
    const float* b2    = (const float*)d_in[11];
    const float* Ws    = (const float*)d_in[12];
    const float* bs    = (const float*)d_in[13];

    float* outO = (float*)d_out;                       // [B,T,D]
    float* outS = outO + (size_t)B_*T_*D_;             // [B,T,D*D]
    float* outZ = outS + (size_t)B_*T_*D_*D_;          // [B,T,D]

    static bool attr_done = false;
    if (!attr_done) {
        cudaFuncSetAttribute(k4_mega, cudaFuncAttributeMaxDynamicSharedMemorySize, SMEM_K4);
        attr_done = true;
    }

    const int smem_k1 = (32*FIN_ + 32*D_) * sizeof(float);   // 49152

    k1_ln_proj<<<dim3((B_*T_)/32, 4), 128, smem_k1>>>(x, gamma, beta, Wk, Wq, Wv, Ws, bs);
    k2_chunksum<<<dim3(C_, B_), 256>>>();
    k3_scan<<<(B_*D_*D_/4 + B_*D_/4 + 255)/256, 256>>>();
    k4_mega<<<dim3(C_, B_), 1024, SMEM_K4>>>(S0, Z0, W1, b1, W2, b2, outO, outS, outZ);
}